// round 11
// baseline (speedup 1.0000x reference)
#include <cuda_runtime.h>
#include <cstdint>

// RoIAlign (TF crop_and_resize) — path-specialized SMEM strides: triple-buffered
// cp.async for the narrow/medium paths at 100% occupancy; 32B-sector-aligned
// demand-sized patches.
// featuremap: (N=2,C=256,H=200,W=304) f32; rois: (M,5); out: (M,256,7,7) f32.
//
// grid = (M, 4): block = (box m, 64-channel slab). warp = channel worker
// (8 channels, stride 8). Patch origin xs is 32B-aligned; row stride (1216B)
// is 32B-divisible => staged rows touch exactly {1,2,3} L2 sectors for the
// {8,16,24}-column paths. Rows fetched = nrows (<=16) the taps need.
//
// SMEM: union buffer of 768 floats/warp (3 KB) -> 24 KB/block -> 8 blocks/SM:
//   path0: stride  8, NBUF=3 (3*128=384 floats)   depth-2 pipeline
//   path1: stride 16, NBUF=3 (3*256=768 floats)   depth-2 pipeline
//   path2: stride 24, NBUF=2 (2*384=768 floats)   depth-1 pipeline
// All strides are multiples of 4 floats => cp.async 16B smem alignment holds.

#define CROP 7
#define NPTS 49
#define C_CH 256
#define H_IM 200
#define W_IM 304
#define PLANE (H_IM * W_IM)
#define WBUF 768                   // floats per warp buffer (union of all paths)
#define CH_PER_BLK 64
#define CH_PER_WARP 8

__device__ __forceinline__ void cp16(unsigned int dst, const float* src) {
    asm volatile("cp.async.cg.shared.global [%0], [%1], 16;\n"
                 :: "r"(dst), "l"(src));
}
__device__ __forceinline__ void cp_commit() {
    asm volatile("cp.async.commit_group;\n" ::: "memory");
}
template <int N>
__device__ __forceinline__ void cp_wait() {
    asm volatile("cp.async.wait_group %0;\n" :: "n"(N) : "memory");
}

struct TapParams {
    int   off_tl[2], off_tr[2], off_bl[2], off_br[2];
    float xlp[2], ylp[2];
    bool  val[2];
};

// NC4 = float4 chunks per row; STRIDE = smem row stride (floats);
// NBUF = ring depth; SLOTS = ceil(16*NC4/32).
template <int NC4, int SLOTS, int STRIDE, int NBUF>
__device__ __forceinline__ void run_channels(
    const float* __restrict__ base,   // img + n*C*PLANE + ys*W + xs
    float* __restrict__ out_m,        // out + m*256*49
    float* __restrict__ sbuf,         // this warp's WBUF floats
    unsigned int sbuf_sh,
    int c_first, int lane, int nchunk,
    const TapParams& tp)
{
    constexpr int PATCH = 16 * STRIDE;

    int g_off[SLOTS], s_off[SLOTS];
    bool ok[SLOTS];
    #pragma unroll
    for (int t = 0; t < SLOTS; ++t) {
        const int e = t * 32 + lane;
        ok[t] = (e < nchunk);
        const int r  = e / NC4;
        const int c4 = e % NC4;
        g_off[t] = r * W_IM + c4 * 4;
        s_off[t] = (r * STRIDE + c4 * 4) * 4;   // bytes
    }

    // prologue: prime NBUF-1 groups
    #pragma unroll
    for (int s = 0; s < NBUF - 1; ++s) {
        const float* pc = base + (size_t)(c_first + s * 8) * PLANE;
        const unsigned int db = sbuf_sh + (unsigned int)(s * (PATCH * 4));
        #pragma unroll
        for (int t = 0; t < SLOTS; ++t)
            if (ok[t]) cp16(db + s_off[t], pc + g_off[t]);
        cp_commit();
    }

    #pragma unroll
    for (int k = 0; k < CH_PER_WARP; ++k) {
        const int c = c_first + k * 8;

        if (NBUF == 3) {
            // depth-2: issue k+2, wait for group k (2 pending after issue)
            if (k + 2 < CH_PER_WARP) {
                const float* pc = base + (size_t)(c + 16) * PLANE;
                const unsigned int db =
                    sbuf_sh + (unsigned int)(((k + 2) % NBUF) * (PATCH * 4));
                #pragma unroll
                for (int t = 0; t < SLOTS; ++t)
                    if (ok[t]) cp16(db + s_off[t], pc + g_off[t]);
                cp_commit();
                cp_wait<2>();
            } else if (k + 1 < CH_PER_WARP) {
                cp_wait<1>();
            } else {
                cp_wait<0>();
            }
            __syncwarp();
        } else {
            // depth-1: wait for k, then issue k+1 overlapped with compute
            cp_wait<0>();
            __syncwarp();
            if (k + 1 < CH_PER_WARP) {
                const float* pc = base + (size_t)(c + 8) * PLANE;
                const unsigned int db =
                    sbuf_sh + (unsigned int)(((k + 1) % NBUF) * (PATCH * 4));
                #pragma unroll
                for (int t = 0; t < SLOTS; ++t)
                    if (ok[t]) cp16(db + s_off[t], pc + g_off[t]);
                cp_commit();
            }
        }

        const float* patch = sbuf + (k % NBUF) * PATCH;
        float* __restrict__ op = out_m + (size_t)c * NPTS;

        // t = 0: p = lane (always < 49)
        {
            float v = 0.0f;
            if (tp.val[0]) {
                const float tl = patch[tp.off_tl[0]];
                const float tr = patch[tp.off_tr[0]];
                const float bl = patch[tp.off_bl[0]];
                const float br = patch[tp.off_br[0]];
                const float top = fmaf(tr - tl, tp.xlp[0], tl);
                const float bot = fmaf(br - bl, tp.xlp[0], bl);
                v = fmaf(bot - top, tp.ylp[0], top);
            }
            op[lane] = v;
        }
        // t = 1: p = lane + 32 (17 active lanes)
        if (lane + 32 < NPTS) {
            float v = 0.0f;
            if (tp.val[1]) {
                const float tl = patch[tp.off_tl[1]];
                const float tr = patch[tp.off_tr[1]];
                const float bl = patch[tp.off_bl[1]];
                const float br = patch[tp.off_br[1]];
                const float top = fmaf(tr - tl, tp.xlp[1], tl);
                const float bot = fmaf(br - bl, tp.xlp[1], bl);
                v = fmaf(bot - top, tp.ylp[1], top);
            }
            op[lane + 32] = v;
        }
        if (NBUF == 3) __syncwarp();   // reads done before buf (k)%3 reuse
    }
}

__global__ void __launch_bounds__(256, 8)
roialign11_kernel(const float* __restrict__ img,
                  const float* __restrict__ rois,
                  const float* __restrict__ scale_p,
                  float* __restrict__ out,
                  int M)
{
    __shared__ __align__(16) float s_patch[8 * WBUF];   // 24 KB

    const int m    = blockIdx.x;
    const int cg   = blockIdx.y;            // channel group (0..3)
    const int tid  = threadIdx.x;
    const int wid  = tid >> 5;
    const int lane = tid & 31;
    if (m >= M) return;

    // ---- block-uniform ROI params ----
    const float scale = *scale_p;
    const float* roi = rois + (size_t)m * 5;
    const int   n   = (int)roi[0];
    const float x1s = roi[1] * scale;
    const float y1s = roi[2] * scale;
    const float sw  = (roi[3] * scale - x1s) * (1.0f / CROP);
    const float sh  = (roi[4] * scale - y1s) * (1.0f / CROP);
    const float xb  = x1s + sw * 0.5f - 0.5f;
    const float yb  = y1s + sh * 0.5f - 0.5f;

    // y extent actually needed by the taps
    const int ylo = min(max((int)floorf(yb), 0), H_IM - 1);
    const int yhi = min(max((int)ceilf(yb + 6.0f * sh), 0), H_IM - 1);
    const int ys  = min(ylo, H_IM - 16);
    const int nrows = yhi - ys + 1;                       // <= 16

    // x extent; 32B-aligned origin; column-path selection {8,16,24}
    const int xlo = min(max((int)floorf(xb), 0), W_IM - 1);
    const int xhi = min(max((int)ceilf(xb + 6.0f * sw), 0), W_IM - 1);
    const int xa   = xlo & ~7;                            // 32B aligned
    const int xs8  = min(xa, W_IM - 8);
    const int xs16 = min(xa, W_IM - 16);
    const int path = ((xhi - xs8) <= 7) ? 0 : ((xhi - xs16) <= 15 ? 1 : 2);
    const int xs   = (path == 0) ? xs8 : (path == 1) ? xs16
                                       : min(xa, W_IM - 24);
    const int sstride = (path == 0) ? 8 : (path == 1) ? 16 : 24;

    // ---- per-lane tap params (points p = lane, lane+32) ----
    TapParams tp;
    #pragma unroll
    for (int t = 0; t < 2; ++t) {
        const int p = lane + t * 32;
        const int pi = (p < NPTS) ? p : 0;
        const int i = pi / CROP;
        const int j = pi % CROP;
        const float x = xb + (float)j * sw;
        const float y = yb + (float)i * sh;
        const bool vy = (y >= 0.0f) && (y <= (float)(H_IM - 1));
        const bool vx = (x >= 0.0f) && (x <= (float)(W_IM - 1));
        const float yf = floorf(y);
        const float xf = floorf(x);
        const int yt = min(max((int)yf, 0), H_IM - 1) - ys;
        const int yB = min(max((int)ceilf(y), 0), H_IM - 1) - ys;
        const int xl = min(max((int)xf, 0), W_IM - 1) - xs;
        const int xr = min(max((int)ceilf(x), 0), W_IM - 1) - xs;
        tp.off_tl[t] = yt * sstride + xl;
        tp.off_tr[t] = yt * sstride + xr;
        tp.off_bl[t] = yB * sstride + xl;
        tp.off_br[t] = yB * sstride + xr;
        tp.ylp[t] = y - yf;
        tp.xlp[t] = x - xf;
        tp.val[t] = vx && vy;
    }

    const float* __restrict__ base =
        img + (size_t)n * C_CH * (size_t)PLANE + (size_t)(ys * W_IM + xs);
    float* __restrict__ out_m = out + (size_t)m * (C_CH * NPTS);

    float* sbuf = s_patch + wid * WBUF;
    const unsigned int sbuf_sh = (unsigned int)__cvta_generic_to_shared(sbuf);
    const int c_first = cg * CH_PER_BLK + wid;

    if (path == 0)
        run_channels<2, 1,  8, 3>(base, out_m, sbuf, sbuf_sh, c_first, lane, nrows * 2, tp);
    else if (path == 1)
        run_channels<4, 2, 16, 3>(base, out_m, sbuf, sbuf_sh, c_first, lane, nrows * 4, tp);
    else
        run_channels<6, 3, 24, 2>(base, out_m, sbuf, sbuf_sh, c_first, lane, nrows * 6, tp);
}

extern "C" void kernel_launch(void* const* d_in, const int* in_sizes, int n_in,
                              void* d_out, int out_size)
{
    const float* img   = (const float*)d_in[0];
    const float* rois  = (const float*)d_in[1];
    const float* scale = (const float*)d_in[2];
    float* out = (float*)d_out;

    const int M = in_sizes[1] / 5;
    dim3 grid(M, C_CH / CH_PER_BLK);
    roialign11_kernel<<<grid, 256>>>(img, rois, scale, out, M);
}

// round 12
// speedup vs baseline: 1.0437x; 1.0437x over previous
#include <cuda_runtime.h>
#include <cstdint>

// RoIAlign (TF crop_and_resize) — R8 configuration (triple-buffered cp.async,
// depth-2 pipeline, stride-24 patches, 32B-sector-aligned demand-sized fetch)
// + evict-first (__stcs) output stores to keep the write stream out of L2's way.
// featuremap: (N=2,C=256,H=200,W=304) f32; rois: (M,5); out: (M,256,7,7) f32.
//
// grid = (M, 4): block = (box m, 64-channel slab). warp = channel worker
// (8 channels, stride 8). Patch origin xs is 32B-aligned; image row stride
// (1216B) is 32B-divisible => staged rows touch exactly {1,2,3} L2 sectors for
// the {8,16,24}-column paths. Rows fetched = nrows (<=16) the taps need.
// SMEM stride fixed at 24 floats for all paths (4-row bank-alias period:
// r*24 mod 32 = 0,24,16,8 -> conflict-benign tap reads; strides 8/16 alias).

#define CROP 7
#define NPTS 49
#define C_CH 256
#define H_IM 200
#define W_IM 304
#define PLANE (H_IM * W_IM)
#define SSTRIDE 24                 // smem row stride (floats)
#define PATCH (16 * SSTRIDE)       // 384 floats
#define NBUF 3
#define CH_PER_BLK 64
#define CH_PER_WARP 8

__device__ __forceinline__ void cp16(unsigned int dst, const float* src) {
    asm volatile("cp.async.cg.shared.global [%0], [%1], 16;\n"
                 :: "r"(dst), "l"(src));
}
__device__ __forceinline__ void cp_commit() {
    asm volatile("cp.async.commit_group;\n" ::: "memory");
}
template <int N>
__device__ __forceinline__ void cp_wait() {
    asm volatile("cp.async.wait_group %0;\n" :: "n"(N) : "memory");
}

struct TapParams {
    int   off_tl[2], off_tr[2], off_bl[2], off_br[2];
    float xlp[2], ylp[2];
    bool  val[2];
};

// NC4 = float4 chunks per row (2/4/6 -> 8/16/24 cols). SLOTS = ceil(16*NC4/32).
template <int NC4, int SLOTS>
__device__ __forceinline__ void run_channels(
    const float* __restrict__ base,   // img + n*C*PLANE + ys*W + xs
    float* __restrict__ out_m,        // out + m*256*49
    float* __restrict__ sbuf,         // this warp's NBUF*PATCH floats
    unsigned int sbuf_sh,
    int c_first, int lane, int nchunk,
    const TapParams& tp)
{
    int g_off[SLOTS], s_off[SLOTS];
    bool ok[SLOTS];
    #pragma unroll
    for (int t = 0; t < SLOTS; ++t) {
        const int e = t * 32 + lane;
        ok[t] = (e < nchunk);
        const int r  = e / NC4;
        const int c4 = e % NC4;
        g_off[t] = r * W_IM + c4 * 4;
        s_off[t] = (r * SSTRIDE + c4 * 4) * 4;   // bytes
    }

    // prologue: issue channels 0 and 1 into buffers 0, 1 (two groups)
    #pragma unroll
    for (int s = 0; s < 2; ++s) {
        const float* pc = base + (size_t)(c_first + s * 8) * PLANE;
        const unsigned int db = sbuf_sh + (unsigned int)(s * (PATCH * 4));
        #pragma unroll
        for (int t = 0; t < SLOTS; ++t)
            if (ok[t]) cp16(db + s_off[t], pc + g_off[t]);
        cp_commit();
    }

    #pragma unroll
    for (int k = 0; k < CH_PER_WARP; ++k) {
        const int c = c_first + k * 8;

        if (k + 2 < CH_PER_WARP) {
            // issue channel k+2 into buffer (k+2)%3 (its readers finished at
            // end of iteration k-1, fenced by the trailing __syncwarp)
            const float* pc = base + (size_t)(c + 16) * PLANE;
            const unsigned int db =
                sbuf_sh + (unsigned int)(((k + 2) % NBUF) * (PATCH * 4));
            #pragma unroll
            for (int t = 0; t < SLOTS; ++t)
                if (ok[t]) cp16(db + s_off[t], pc + g_off[t]);
            cp_commit();
            cp_wait<2>();
        } else if (k + 1 < CH_PER_WARP) {
            cp_wait<1>();
        } else {
            cp_wait<0>();
        }
        __syncwarp();

        const float* patch = sbuf + (k % NBUF) * PATCH;
        float* __restrict__ op = out_m + (size_t)c * NPTS;

        // t = 0: p = lane (always < 49)
        {
            float v = 0.0f;
            if (tp.val[0]) {
                const float tl = patch[tp.off_tl[0]];
                const float tr = patch[tp.off_tr[0]];
                const float bl = patch[tp.off_bl[0]];
                const float br = patch[tp.off_br[0]];
                const float top = fmaf(tr - tl, tp.xlp[0], tl);
                const float bot = fmaf(br - bl, tp.xlp[0], bl);
                v = fmaf(bot - top, tp.ylp[0], top);
            }
            __stcs(op + lane, v);            // evict-first: write-once stream
        }
        // t = 1: p = lane + 32 (17 active lanes)
        if (lane + 32 < NPTS) {
            float v = 0.0f;
            if (tp.val[1]) {
                const float tl = patch[tp.off_tl[1]];
                const float tr = patch[tp.off_tr[1]];
                const float bl = patch[tp.off_bl[1]];
                const float br = patch[tp.off_br[1]];
                const float top = fmaf(tr - tl, tp.xlp[1], tl);
                const float bot = fmaf(br - bl, tp.xlp[1], bl);
                v = fmaf(bot - top, tp.ylp[1], top);
            }
            __stcs(op + lane + 32, v);       // evict-first
        }
        __syncwarp();
    }
}

__global__ void __launch_bounds__(256)
roialign12_kernel(const float* __restrict__ img,
                  const float* __restrict__ rois,
                  const float* __restrict__ scale_p,
                  float* __restrict__ out,
                  int M)
{
    __shared__ __align__(16) float s_patch[8 * NBUF * PATCH];   // 36 KB

    const int m    = blockIdx.x;
    const int cg   = blockIdx.y;            // channel group (0..3)
    const int tid  = threadIdx.x;
    const int wid  = tid >> 5;
    const int lane = tid & 31;
    if (m >= M) return;

    // ---- block-uniform ROI params ----
    const float scale = *scale_p;
    const float* roi = rois + (size_t)m * 5;
    const int   n   = (int)roi[0];
    const float x1s = roi[1] * scale;
    const float y1s = roi[2] * scale;
    const float sw  = (roi[3] * scale - x1s) * (1.0f / CROP);
    const float sh  = (roi[4] * scale - y1s) * (1.0f / CROP);
    const float xb  = x1s + sw * 0.5f - 0.5f;
    const float yb  = y1s + sh * 0.5f - 0.5f;

    // y extent actually needed by the taps
    const int ylo = min(max((int)floorf(yb), 0), H_IM - 1);
    const int yhi = min(max((int)ceilf(yb + 6.0f * sh), 0), H_IM - 1);
    const int ys  = min(ylo, H_IM - 16);
    const int nrows = yhi - ys + 1;                       // <= 16

    // x extent; 32B-aligned origin; column-path selection {8,16,24}
    const int xlo = min(max((int)floorf(xb), 0), W_IM - 1);
    const int xhi = min(max((int)ceilf(xb + 6.0f * sw), 0), W_IM - 1);
    const int xa   = xlo & ~7;                            // 32B aligned
    const int xs8  = min(xa, W_IM - 8);
    const int xs16 = min(xa, W_IM - 16);
    const int path = ((xhi - xs8) <= 7) ? 0 : ((xhi - xs16) <= 15 ? 1 : 2);
    const int xs   = (path == 0) ? xs8 : (path == 1) ? xs16
                                       : min(xa, W_IM - 24);

    // ---- per-lane tap params (points p = lane, lane+32) ----
    TapParams tp;
    #pragma unroll
    for (int t = 0; t < 2; ++t) {
        const int p = lane + t * 32;
        const int pi = (p < NPTS) ? p : 0;
        const int i = pi / CROP;
        const int j = pi % CROP;
        const float x = xb + (float)j * sw;
        const float y = yb + (float)i * sh;
        const bool vy = (y >= 0.0f) && (y <= (float)(H_IM - 1));
        const bool vx = (x >= 0.0f) && (x <= (float)(W_IM - 1));
        const float yf = floorf(y);
        const float xf = floorf(x);
        const int yt = min(max((int)yf, 0), H_IM - 1) - ys;
        const int yB = min(max((int)ceilf(y), 0), H_IM - 1) - ys;
        const int xl = min(max((int)xf, 0), W_IM - 1) - xs;
        const int xr = min(max((int)ceilf(x), 0), W_IM - 1) - xs;
        tp.off_tl[t] = yt * SSTRIDE + xl;
        tp.off_tr[t] = yt * SSTRIDE + xr;
        tp.off_bl[t] = yB * SSTRIDE + xl;
        tp.off_br[t] = yB * SSTRIDE + xr;
        tp.ylp[t] = y - yf;
        tp.xlp[t] = x - xf;
        tp.val[t] = vx && vy;
    }

    const float* __restrict__ base =
        img + (size_t)n * C_CH * (size_t)PLANE + (size_t)(ys * W_IM + xs);
    float* __restrict__ out_m = out + (size_t)m * (C_CH * NPTS);

    float* sbuf = s_patch + wid * (NBUF * PATCH);
    const unsigned int sbuf_sh = (unsigned int)__cvta_generic_to_shared(sbuf);
    const int c_first = cg * CH_PER_BLK + wid;

    if (path == 0)
        run_channels<2, 1>(base, out_m, sbuf, sbuf_sh, c_first, lane, nrows * 2, tp);
    else if (path == 1)
        run_channels<4, 2>(base, out_m, sbuf, sbuf_sh, c_first, lane, nrows * 4, tp);
    else
        run_channels<6, 3>(base, out_m, sbuf, sbuf_sh, c_first, lane, nrows * 6, tp);
}

extern "C" void kernel_launch(void* const* d_in, const int* in_sizes, int n_in,
                              void* d_out, int out_size)
{
    const float* img   = (const float*)d_in[0];
    const float* rois  = (const float*)d_in[1];
    const float* scale = (const float*)d_in[2];
    float* out = (float*)d_out;

    const int M = in_sizes[1] / 5;
    dim3 grid(M, C_CH / CH_PER_BLK);
    roialign12_kernel<<<grid, 256>>>(img, rois, scale, out, M);
}